// round 15
// baseline (speedup 1.0000x reference)
#include <cuda_runtime.h>
#include <cuda_bf16.h>
#include <cstdint>
#include <math.h>

#define B_   2
#define S_   2048
#define D_   1024
#define H_   16
#define HD_  64
#define MTOT (B_ * S_)        // 4096

// Scratch (__device__ globals; no cudaMalloc allowed)
__device__ __nv_bfloat16 g_qkvh[MTOT * 3 * D_];   // qkv hi  (25 MB)
__device__ __nv_bfloat16 g_qkvl[MTOT * 3 * D_];   // qkv lo  (25 MB)
__device__ __nv_bfloat16 g_ahi[MTOT * D_];        // A-split hi (x, then att out)
__device__ __nv_bfloat16 g_alo[MTOT * D_];        // A-split lo
__device__ __nv_bfloat16 g_bthi[3 * D_ * D_];     // W^T hi [N][K]
__device__ __nv_bfloat16 g_btlo[3 * D_ * D_];     // W^T lo

// ---------------------------------------------------------------------------
// helpers
// ---------------------------------------------------------------------------
__device__ __forceinline__ uint32_t smem_u32(const void* p) {
    uint32_t a;
    asm("{ .reg .u64 t; cvta.to.shared.u64 t, %1; cvt.u32.u64 %0, t; }"
        : "=r"(a) : "l"(p));
    return a;
}

#define LDSM4(r0, r1, r2, r3, addr) \
    asm volatile("ldmatrix.sync.aligned.m8n8.x4.shared.b16 {%0,%1,%2,%3}, [%4];" \
                 : "=r"(r0), "=r"(r1), "=r"(r2), "=r"(r3) : "r"(addr))
#define LDSM4T(r0, r1, r2, r3, addr) \
    asm volatile("ldmatrix.sync.aligned.m8n8.x4.trans.shared.b16 {%0,%1,%2,%3}, [%4];" \
                 : "=r"(r0), "=r"(r1), "=r"(r2), "=r"(r3) : "r"(addr))

#define MMA_BF16(c, a, b) \
    asm volatile("mma.sync.aligned.m16n8k16.row.col.f32.bf16.bf16.f32 " \
                 "{%0,%1,%2,%3}, {%4,%5,%6,%7}, {%8,%9}, {%0,%1,%2,%3};" \
                 : "+f"((c)[0]), "+f"((c)[1]), "+f"((c)[2]), "+f"((c)[3]) \
                 : "r"((a)[0]), "r"((a)[1]), "r"((a)[2]), "r"((a)[3]), \
                   "r"((b)[0]), "r"((b)[1]))

#define CP16(dst, src) \
    asm volatile("cp.async.cg.shared.global [%0], [%1], 16;" \
                 :: "r"(dst), "l"(src))
#define CP_COMMIT() asm volatile("cp.async.commit_group;" ::: "memory")
#define CP_WAIT0()  asm volatile("cp.async.wait_group 0;" ::: "memory")

__device__ __forceinline__ uint32_t pack_bf16(float a, float b) {
    __nv_bfloat162 t = __floats2bfloat162_rn(a, b);
    return *reinterpret_cast<uint32_t*>(&t);
}

// split a pair into hi bf16x2 + lo (residual) bf16x2
__device__ __forceinline__ void pack2_split(float a, float b,
                                            uint32_t& hi, uint32_t& lo) {
    __nv_bfloat162 h = __floats2bfloat162_rn(a, b);
    hi = *reinterpret_cast<uint32_t*>(&h);
    float ha = __bfloat162float(h.x), hb = __bfloat162float(h.y);
    __nv_bfloat162 l = __floats2bfloat162_rn(a - ha, b - hb);
    lo = *reinterpret_cast<uint32_t*>(&l);
}

// ---------------------------------------------------------------------------
// Prep: split fp32 -> bf16 hi/lo  (rowwise, [M][K] layout preserved)
// ---------------------------------------------------------------------------
__global__ void split_bf16(const float* __restrict__ src,
                           __nv_bfloat16* __restrict__ hi,
                           __nv_bfloat16* __restrict__ lo, int n4) {
    int i = blockIdx.x * blockDim.x + threadIdx.x;
    if (i >= n4) return;
    float4 v = ((const float4*)src)[i];
    float h0 = __bfloat162float(__float2bfloat16_rn(v.x));
    float h1 = __bfloat162float(__float2bfloat16_rn(v.y));
    float h2 = __bfloat162float(__float2bfloat16_rn(v.z));
    float h3 = __bfloat162float(__float2bfloat16_rn(v.w));
    uint2 ho, lw;
    ho.x = pack_bf16(h0, h1);
    ho.y = pack_bf16(h2, h3);
    lw.x = pack_bf16(v.x - h0, v.y - h1);
    lw.y = pack_bf16(v.z - h2, v.w - h3);
    ((uint2*)hi)[i] = ho;
    ((uint2*)lo)[i] = lw;
}

// Prep: W[K][N] fp32 -> W^T hi/lo bf16 [N][K]
__global__ void transpose_split_bf16(const float* __restrict__ W,
                                     __nv_bfloat16* __restrict__ Thi,
                                     __nv_bfloat16* __restrict__ Tlo,
                                     int K, int N) {
    __shared__ float t[32][33];
    int n0 = blockIdx.x * 32, k0 = blockIdx.y * 32;
    int tx = threadIdx.x, ty = threadIdx.y;   // 32 x 8
#pragma unroll
    for (int i = 0; i < 4; i++)
        t[ty + 8 * i][tx] = W[(size_t)(k0 + ty + 8 * i) * N + n0 + tx];
    __syncthreads();
#pragma unroll
    for (int i = 0; i < 4; i++) {
        float v = t[tx][ty + 8 * i];
        float h = __bfloat162float(__float2bfloat16_rn(v));
        size_t o = (size_t)(n0 + ty + 8 * i) * K + k0 + tx;
        Thi[o] = __float2bfloat16_rn(h);
        Tlo[o] = __float2bfloat16_rn(v - h);
    }
}

// ---------------------------------------------------------------------------
// Tensor-core GEMM: C = A @ W + bias, bf16 x3 split. x4 B-fragments, occ 2.
// SPLIT=true: write result as bf16 hi/lo pair (Chi/Clo); else fp32 C.
// ---------------------------------------------------------------------------
#define BKP 40
#define MATB (128 * BKP * 2)
#define BUFB (4 * MATB)
#define GEMM_SMEM (2 * BUFB)

template <bool SPLIT>
__global__ __launch_bounds__(256, 2)
void gemm_bf16x3(const __nv_bfloat16* __restrict__ Ahi,
                 const __nv_bfloat16* __restrict__ Alo,
                 const __nv_bfloat16* __restrict__ Bhi,
                 const __nv_bfloat16* __restrict__ Blo,
                 const float* __restrict__ bias, float* __restrict__ C,
                 __nv_bfloat16* __restrict__ Chi,
                 __nv_bfloat16* __restrict__ Clo,
                 int M, int N, int K) {
    extern __shared__ char smraw[];
    const int tid  = threadIdx.x;
    const int lane = tid & 31;
    const int wid  = tid >> 5;
    const int m0   = blockIdx.y * 128;
    const int n0   = blockIdx.x * 128;
    const int m0w  = (wid >> 2) * 64;
    const int n0w  = (wid & 3) * 32;
    const uint32_t sb = smem_u32(smraw);

    const int lrow = tid >> 1;
    const int lk   = (tid & 1) * 16;
    const __nv_bfloat16* gAh = Ahi + (size_t)(m0 + lrow) * K + lk;
    const __nv_bfloat16* gAl = Alo + (size_t)(m0 + lrow) * K + lk;
    const __nv_bfloat16* gBh = Bhi + (size_t)(n0 + lrow) * K + lk;
    const __nv_bfloat16* gBl = Blo + (size_t)(n0 + lrow) * K + lk;
    const uint32_t sdst = (uint32_t)(lrow * (BKP * 2) + lk * 2);

    float c[4][4][4] = {};

    const int arow = lane & 15;
    const int acol = (lane >> 4) * 8;
    // x4 B-fragment lane mapping: 16 n-rows x k16 per LDSM4
    const int bnr  = (lane >> 4) * 8 + (lane & 7);   // n-row within 16
    const int bk8  = ((lane >> 3) & 1) * 8;          // k +0 / +8

    {
        uint4 a0 = *(const uint4*)(gAh);     uint4 a1 = *(const uint4*)(gAh + 8);
        uint4 l0 = *(const uint4*)(gAl);     uint4 l1 = *(const uint4*)(gAl + 8);
        uint4 b0 = *(const uint4*)(gBh);     uint4 b1 = *(const uint4*)(gBh + 8);
        uint4 w0 = *(const uint4*)(gBl);     uint4 w1 = *(const uint4*)(gBl + 8);
        char* p = smraw;
        *(uint4*)(p + 0 * MATB + sdst) = a0;  *(uint4*)(p + 0 * MATB + sdst + 16) = a1;
        *(uint4*)(p + 1 * MATB + sdst) = l0;  *(uint4*)(p + 1 * MATB + sdst + 16) = l1;
        *(uint4*)(p + 2 * MATB + sdst) = b0;  *(uint4*)(p + 2 * MATB + sdst + 16) = b1;
        *(uint4*)(p + 3 * MATB + sdst) = w0;  *(uint4*)(p + 3 * MATB + sdst + 16) = w1;
    }
    __syncthreads();

    int buf = 0;
    for (int k0 = 32; k0 <= K; k0 += 32) {
        uint4 a0, a1, l0, l1, b0, b1, w0, w1;
        const bool more = (k0 < K);
        if (more) {
            a0 = *(const uint4*)(gAh + k0); a1 = *(const uint4*)(gAh + k0 + 8);
            l0 = *(const uint4*)(gAl + k0); l1 = *(const uint4*)(gAl + k0 + 8);
            b0 = *(const uint4*)(gBh + k0); b1 = *(const uint4*)(gBh + k0 + 8);
            w0 = *(const uint4*)(gBl + k0); w1 = *(const uint4*)(gBl + k0 + 8);
        }

        const uint32_t bb = sb + (uint32_t)buf * BUFB;
#pragma unroll
        for (int ks = 0; ks < 2; ks++) {
            uint32_t bh4[2][4], bl4[2][4];
#pragma unroll
            for (int nt2 = 0; nt2 < 2; nt2++) {
                uint32_t boff = (uint32_t)((n0w + nt2 * 16 + bnr) * (BKP * 2)
                                           + (ks * 16 + bk8) * 2);
                LDSM4(bh4[nt2][0], bh4[nt2][1], bh4[nt2][2], bh4[nt2][3],
                      bb + 2 * MATB + boff);
                LDSM4(bl4[nt2][0], bl4[nt2][1], bl4[nt2][2], bl4[nt2][3],
                      bb + 3 * MATB + boff);
            }
#pragma unroll
            for (int mt = 0; mt < 4; mt++) {
                uint32_t aoff = (uint32_t)((m0w + mt * 16 + arow) * (BKP * 2)
                                           + (ks * 16 + acol) * 2);
                uint32_t ah[4], al[4];
                LDSM4(ah[0], ah[1], ah[2], ah[3], bb + 0 * MATB + aoff);
                LDSM4(al[0], al[1], al[2], al[3], bb + 1 * MATB + aoff);
#pragma unroll
                for (int nt = 0; nt < 4; nt++) {
                    uint32_t* bh = bh4[nt >> 1] + (nt & 1) * 2;
                    uint32_t* bl = bl4[nt >> 1] + (nt & 1) * 2;
                    MMA_BF16(c[mt][nt], ah, bh);
                    MMA_BF16(c[mt][nt], ah, bl);
                    MMA_BF16(c[mt][nt], al, bh);
                }
            }
        }

        if (more) {
            char* p = smraw + (buf ^ 1) * BUFB;
            *(uint4*)(p + 0 * MATB + sdst) = a0;  *(uint4*)(p + 0 * MATB + sdst + 16) = a1;
            *(uint4*)(p + 1 * MATB + sdst) = l0;  *(uint4*)(p + 1 * MATB + sdst + 16) = l1;
            *(uint4*)(p + 2 * MATB + sdst) = b0;  *(uint4*)(p + 2 * MATB + sdst + 16) = b1;
            *(uint4*)(p + 3 * MATB + sdst) = w0;  *(uint4*)(p + 3 * MATB + sdst + 16) = w1;
            __syncthreads();
            buf ^= 1;
        }
    }

    const int erow = lane >> 2;
    const int ecol = (lane & 3) * 2;
#pragma unroll
    for (int mt = 0; mt < 4; mt++) {
#pragma unroll
        for (int nt = 0; nt < 4; nt++) {
            const int col = n0 + n0w + nt * 8 + ecol;
            const float bi0 = bias[col], bi1 = bias[col + 1];
            const int r0 = m0 + m0w + mt * 16 + erow;
            float v00 = c[mt][nt][0] + bi0, v01 = c[mt][nt][1] + bi1;
            float v10 = c[mt][nt][2] + bi0, v11 = c[mt][nt][3] + bi1;
            if (SPLIT) {
                uint32_t h0, l0v, h1, l1v;
                pack2_split(v00, v01, h0, l0v);
                pack2_split(v10, v11, h1, l1v);
                *(uint32_t*)(Chi + (size_t)r0 * N + col) = h0;
                *(uint32_t*)(Clo + (size_t)r0 * N + col) = l0v;
                *(uint32_t*)(Chi + (size_t)(r0 + 8) * N + col) = h1;
                *(uint32_t*)(Clo + (size_t)(r0 + 8) * N + col) = l1v;
            } else {
                float2 v0, v1;
                v0.x = v00; v0.y = v01;
                v1.x = v10; v1.y = v11;
                *(float2*)(C + (size_t)r0 * N + col) = v0;
                *(float2*)(C + (size_t)(r0 + 8) * N + col) = v1;
            }
        }
    }
}

// ---------------------------------------------------------------------------
// Tensor-core flash attention v4: split-K warps + x4 ldmatrix everywhere.
// 512 threads (16 warps). Warp (qg = wid>>1, kh = wid&1) owns q rows
// qg*16..+15 and k cols kh*64..+63 per 128-k tile; states combined at end.
// smem: Qh,Ql + 2 x (Kh,Kl,Vh,Vl), each [128][72] bf16 = 184320 B.
// ---------------------------------------------------------------------------
#define QP 72
#define TILEB (128 * QP)                  // bf16 elems per matrix
#define ATTN_SMEM ((2 + 8) * TILEB * 2)   // 184320 bytes

__global__ __launch_bounds__(512, 1)
void attention_mma(const __nv_bfloat16* __restrict__ qg_h,
                   const __nv_bfloat16* __restrict__ qg_l,
                   __nv_bfloat16* __restrict__ ohi,
                   __nv_bfloat16* __restrict__ olo) {
    extern __shared__ __nv_bfloat16 smb[];
    __nv_bfloat16* Qh = smb;
    __nv_bfloat16* Ql = Qh + TILEB;
    __nv_bfloat16* KV = Ql + TILEB;       // [buf][mat: Kh,Kl,Vh,Vl][TILEB]

    const int tid  = threadIdx.x;
    const int lane = tid & 31;
    const int wid  = tid >> 5;
    const int l16  = lane & 15;
    const int qg   = wid >> 1;            // q group 0..7
    const int kh   = wid & 1;             // k half 0..1
    const int qr0  = qg * 16;

    const int bb = blockIdx.x >> 4;       // batch
    const int h  = blockIdx.x & 15;
    const int q0 = blockIdx.y * 128;

    const int qoff = h * HD_;
    const int koff = D_ + h * HD_;
    const int voff = 2 * D_ + h * HD_;

    // loader: 512 threads, row lr = tid>>2 (0..127), chunks ch0,ch0+1 of 8
    const int lr   = tid >> 2;
    const int ch0  = (tid & 3) * 2;       // 16B-chunk index: 0,2,4,6
    const uint32_t sQh = smem_u32(Qh) + (uint32_t)(lr * QP + ch0 * 8) * 2;
    const uint32_t sQl = smem_u32(Ql) + (uint32_t)(lr * QP + ch0 * 8) * 2;
    const uint32_t sKV = smem_u32(KV) + (uint32_t)(lr * QP + ch0 * 8) * 2;

    // ---- prologue: Q + KV tile 0 ----
    {
        const size_t qrow = (size_t)(bb * S_ + q0 + lr) * (3 * D_) + qoff + ch0 * 8;
#pragma unroll
        for (int i = 0; i < 2; i++) {
            CP16(sQh + i * 16, qg_h + qrow + i * 8);
            CP16(sQl + i * 16, qg_l + qrow + i * 8);
        }
        const size_t krow = (size_t)(bb * S_ + lr) * (3 * D_);
#pragma unroll
        for (int i = 0; i < 2; i++) {
            CP16(sKV + 0 * TILEB * 2 + i * 16, qg_h + krow + koff + ch0 * 8 + i * 8);
            CP16(sKV + 1 * TILEB * 2 + i * 16, qg_l + krow + koff + ch0 * 8 + i * 8);
            CP16(sKV + 2 * TILEB * 2 + i * 16, qg_h + krow + voff + ch0 * 8 + i * 8);
            CP16(sKV + 3 * TILEB * 2 + i * 16, qg_l + krow + voff + ch0 * 8 + i * 8);
        }
        CP_COMMIT();
    }
    CP_WAIT0();
    __syncthreads();

    // ---- Q fragments (persistent) ----
    uint32_t qh[4][4], ql[4][4];
#pragma unroll
    for (int ks = 0; ks < 4; ks++) {
        uint32_t ao = (uint32_t)((qr0 + l16) * QP + ks * 16 + (lane >> 4) * 8) * 2;
        LDSM4(qh[ks][0], qh[ks][1], qh[ks][2], qh[ks][3], smem_u32(Qh) + ao);
        LDSM4(ql[ks][0], ql[ks][1], ql[ks][2], ql[ks][3], smem_u32(Ql) + ao);
    }

    float O[8][4] = {};
    float m0 = -1e30f, m1 = -1e30f, l0 = 0.f, l1 = 0.f;
    const float scale = 0.125f;

    // x4 lane-address components
    const int kbrow = (lane >> 4) * 8 + (lane & 7);   // n-row within 16
    const int kbk8  = ((lane >> 3) & 1) * 8;          // k +0/+8
    const int vbrow = lane & 15;                      // k-row within 16
    const int vbc8  = (lane >> 4) * 8;                // col +0/+8

    int buf = 0;
    for (int kt = 0; kt < S_ / 128; kt++) {
        CP_WAIT0();          // KV(kt) resident
        __syncthreads();     // visible to all; all threads done with buf^1

        // issue KV(kt+1) into buf^1 (overlaps with compute below)
        if (kt + 1 < S_ / 128) {
            const size_t krow = (size_t)(bb * S_ + (kt + 1) * 128 + lr) * (3 * D_);
            const uint32_t d = sKV + (uint32_t)(buf ^ 1) * 4 * TILEB * 2;
#pragma unroll
            for (int i = 0; i < 2; i++) {
                CP16(d + 0 * TILEB * 2 + i * 16, qg_h + krow + koff + ch0 * 8 + i * 8);
                CP16(d + 1 * TILEB * 2 + i * 16, qg_l + krow + koff + ch0 * 8 + i * 8);
                CP16(d + 2 * TILEB * 2 + i * 16, qg_h + krow + voff + ch0 * 8 + i * 8);
                CP16(d + 3 * TILEB * 2 + i * 16, qg_l + krow + voff + ch0 * 8 + i * 8);
            }
            CP_COMMIT();
        }

        const __nv_bfloat16* Kh = KV + (size_t)buf * 4 * TILEB;
        const __nv_bfloat16* Kl = Kh + TILEB;
        const __nv_bfloat16* Vh = Kl + TILEB;
        const __nv_bfloat16* Vl = Vh + TILEB;
        const uint32_t kb4_h = smem_u32(Kh)
            + (uint32_t)((kh * 64 + kbrow) * QP + kbk8) * 2;
        const uint32_t kb4_l = smem_u32(Kl)
            + (uint32_t)((kh * 64 + kbrow) * QP + kbk8) * 2;
        const uint32_t vb4_h = smem_u32(Vh)
            + (uint32_t)((kh * 64 + vbrow) * QP + vbc8) * 2;
        const uint32_t vb4_l = smem_u32(Vl)
            + (uint32_t)((kh * 64 + vbrow) * QP + vbc8) * 2;

        // ---- S = QK^T over 64 cols (3-term split, x4 B-frags) ----
        float s[8][4];
#pragma unroll
        for (int nf2 = 0; nf2 < 4; nf2++) {
            float* s0 = s[2 * nf2];
            float* s1 = s[2 * nf2 + 1];
            s0[0] = s0[1] = s0[2] = s0[3] = 0.f;
            s1[0] = s1[1] = s1[2] = s1[3] = 0.f;
#pragma unroll
            for (int ks = 0; ks < 4; ks++) {
                const uint32_t off = (uint32_t)(nf2 * 16 * QP + ks * 16) * 2;
                uint32_t bh[4], bl[4];
                LDSM4(bh[0], bh[1], bh[2], bh[3], kb4_h + off);
                LDSM4(bl[0], bl[1], bl[2], bl[3], kb4_l + off);
                MMA_BF16(s0, qh[ks], bh);
                MMA_BF16(s0, qh[ks], bl);
                MMA_BF16(s0, ql[ks], bh);
                MMA_BF16(s1, qh[ks], bh + 2);
                MMA_BF16(s1, qh[ks], bl + 2);
                MMA_BF16(s1, ql[ks], bh + 2);
            }
        }

        // ---- online softmax on fragments ----
        float mx0 = -1e30f, mx1 = -1e30f;
#pragma unroll
        for (int nf = 0; nf < 8; nf++) {
            s[nf][0] *= scale; s[nf][1] *= scale;
            s[nf][2] *= scale; s[nf][3] *= scale;
            mx0 = fmaxf(mx0, fmaxf(s[nf][0], s[nf][1]));
            mx1 = fmaxf(mx1, fmaxf(s[nf][2], s[nf][3]));
        }
        mx0 = fmaxf(mx0, __shfl_xor_sync(0xffffffffu, mx0, 1));
        mx0 = fmaxf(mx0, __shfl_xor_sync(0xffffffffu, mx0, 2));
        mx1 = fmaxf(mx1, __shfl_xor_sync(0xffffffffu, mx1, 1));
        mx1 = fmaxf(mx1, __shfl_xor_sync(0xffffffffu, mx1, 2));

        const float mn0 = fmaxf(m0, mx0);
        const float mn1 = fmaxf(m1, mx1);
        const float al0 = __expf(m0 - mn0);
        const float al1 = __expf(m1 - mn1);
        m0 = mn0; m1 = mn1;

        float rs0 = 0.f, rs1 = 0.f;
#pragma unroll
        for (int nf = 0; nf < 8; nf++) {
            s[nf][0] = __expf(s[nf][0] - m0);
            s[nf][1] = __expf(s[nf][1] - m0);
            s[nf][2] = __expf(s[nf][2] - m1);
            s[nf][3] = __expf(s[nf][3] - m1);
            rs0 += s[nf][0] + s[nf][1];
            rs1 += s[nf][2] + s[nf][3];
        }
        rs0 += __shfl_xor_sync(0xffffffffu, rs0, 1);
        rs0 += __shfl_xor_sync(0xffffffffu, rs0, 2);
        rs1 += __shfl_xor_sync(0xffffffffu, rs1, 1);
        rs1 += __shfl_xor_sync(0xffffffffu, rs1, 2);
        l0 = l0 * al0 + rs0;
        l1 = l1 * al1 + rs1;

#pragma unroll
        for (int df = 0; df < 8; df++) {
            O[df][0] *= al0; O[df][1] *= al0;
            O[df][2] *= al1; O[df][3] *= al1;
        }

        // ---- O += P @ V over this warp's 64 k-rows (x4 trans V-frags) ----
#pragma unroll
        for (int kk = 0; kk < 4; kk++) {
            uint32_t ah[4], alr[4];
            pack2_split(s[2 * kk][0],     s[2 * kk][1],     ah[0], alr[0]);
            pack2_split(s[2 * kk][2],     s[2 * kk][3],     ah[1], alr[1]);
            pack2_split(s[2 * kk + 1][0], s[2 * kk + 1][1], ah[2], alr[2]);
            pack2_split(s[2 * kk + 1][2], s[2 * kk + 1][3], ah[3], alr[3]);
#pragma unroll
            for (int df2 = 0; df2 < 4; df2++) {
                const uint32_t off = (uint32_t)(kk * 16 * QP + df2 * 16) * 2;
                uint32_t vh4[4], vl4[4];
                LDSM4T(vh4[0], vh4[1], vh4[2], vh4[3], vb4_h + off);
                LDSM4T(vl4[0], vl4[1], vl4[2], vl4[3], vb4_l + off);
                MMA_BF16(O[2 * df2],     ah,  vh4);
                MMA_BF16(O[2 * df2],     ah,  vl4);
                MMA_BF16(O[2 * df2],     alr, vh4);
                MMA_BF16(O[2 * df2 + 1], ah,  vh4 + 2);
                MMA_BF16(O[2 * df2 + 1], ah,  vl4 + 2);
                MMA_BF16(O[2 * df2 + 1], alr, vh4 + 2);
            }
        }
        buf ^= 1;
    }

    // ---- combine the two k-half states per q-group (via reused KV smem) ----
    __syncthreads();                       // all compute done; smem reusable
    float* mlb = (float*)smb;              // [8 g][2 kh][16 row][2 (m,l)]
    float* Ost = (float*)smb + 1024;       // [8 g][16 row][64 col]

    const int r = lane >> 2;
    if ((lane & 3) == 0) {
        float* p = mlb + ((qg * 2 + kh) * 16 + r) * 2;
        p[0] = m0;  p[1] = l0;
        float* p8 = mlb + ((qg * 2 + kh) * 16 + r + 8) * 2;
        p8[0] = m1; p8[1] = l1;
    }
    __syncthreads();

    const float* pa0 = mlb + ((qg * 2 + 0) * 16 + r) * 2;
    const float* pb0 = mlb + ((qg * 2 + 1) * 16 + r) * 2;
    const float* pa1 = mlb + ((qg * 2 + 0) * 16 + r + 8) * 2;
    const float* pb1 = mlb + ((qg * 2 + 1) * 16 + r + 8) * 2;
    const float ma0 = pa0[0], la0 = pa0[1], mb0 = pb0[0], lb0 = pb0[1];
    const float ma1 = pa1[0], la1 = pa1[1], mb1 = pb1[0], lb1 = pb1[1];
    const float mm0 = fmaxf(ma0, mb0), mm1 = fmaxf(ma1, mb1);
    const float fa0 = __expf(ma0 - mm0), fb0 = __expf(mb0 - mm0);
    const float fa1 = __expf(ma1 - mm1), fb1 = __expf(mb1 - mm1);
    const float lc0 = la0 * fa0 + lb0 * fb0;
    const float lc1 = la1 * fa1 + lb1 * fb1;

    const int ccol = (lane & 3) * 2;
    if (kh == 1) {                         // stage scaled O of half 1
#pragma unroll
        for (int df = 0; df < 8; df++) {
            float* p0 = Ost + (qg * 16 + r) * 64 + df * 8 + ccol;
            float* p1 = Ost + (qg * 16 + r + 8) * 64 + df * 8 + ccol;
            p0[0] = O[df][0] * fb0;  p0[1] = O[df][1] * fb0;
            p1[0] = O[df][2] * fb1;  p1[1] = O[df][3] * fb1;
        }
    }
    __syncthreads();

    if (kh == 0) {                         // merge + normalize + split-store
        const float inv0 = 1.f / lc0;
        const float inv1 = 1.f / lc1;
        const int qrow = q0 + qr0 + r;
        const int cb   = h * HD_ + ccol;
#pragma unroll
        for (int df = 0; df < 8; df++) {
            const float* p0 = Ost + (qg * 16 + r) * 64 + df * 8 + ccol;
            const float* p1 = Ost + (qg * 16 + r + 8) * 64 + df * 8 + ccol;
            float v00 = (O[df][0] * fa0 + p0[0]) * inv0;
            float v01 = (O[df][1] * fa0 + p0[1]) * inv0;
            float v10 = (O[df][2] * fa1 + p1[0]) * inv1;
            float v11 = (O[df][3] * fa1 + p1[1]) * inv1;
            uint32_t h0, lv0, h1, lv1;
            pack2_split(v00, v01, h0, lv0);
            pack2_split(v10, v11, h1, lv1);
            const size_t r0 = (size_t)(bb * S_ + qrow) * D_ + cb + df * 8;
            const size_t r1 = (size_t)(bb * S_ + qrow + 8) * D_ + cb + df * 8;
            *(uint32_t*)(ohi + r0) = h0;
            *(uint32_t*)(olo + r0) = lv0;
            *(uint32_t*)(ohi + r1) = h1;
            *(uint32_t*)(olo + r1) = lv1;
        }
    }
}

// ---------------------------------------------------------------------------
extern "C" void kernel_launch(void* const* d_in, const int* in_sizes, int n_in,
                              void* d_out, int out_size) {
    const float* x     = (const float*)d_in[0];
    const float* Wqkv  = (const float*)d_in[1];
    const float* bqkv  = (const float*)d_in[2];
    const float* Wproj = (const float*)d_in[3];
    const float* bproj = (const float*)d_in[4];
    float* out = (float*)d_out;

    __nv_bfloat16 *qkvh, *qkvl, *ahi, *alo, *bthi, *btlo;
    cudaGetSymbolAddress((void**)&qkvh, g_qkvh);
    cudaGetSymbolAddress((void**)&qkvl, g_qkvl);
    cudaGetSymbolAddress((void**)&ahi,  g_ahi);
    cudaGetSymbolAddress((void**)&alo,  g_alo);
    cudaGetSymbolAddress((void**)&bthi, g_bthi);
    cudaGetSymbolAddress((void**)&btlo, g_btlo);

    cudaFuncSetAttribute(attention_mma,
                         cudaFuncAttributeMaxDynamicSharedMemorySize, ATTN_SMEM);
    cudaFuncSetAttribute(gemm_bf16x3<true>,
                         cudaFuncAttributeMaxDynamicSharedMemorySize, GEMM_SMEM);
    cudaFuncSetAttribute(gemm_bf16x3<false>,
                         cudaFuncAttributeMaxDynamicSharedMemorySize, GEMM_SMEM);

    const int n4 = MTOT * D_ / 4;

    // 1) prep: split x; transpose+split Wqkv -> [3072][1024]
    split_bf16<<<(n4 + 255) / 256, 256>>>(x, ahi, alo, n4);
    transpose_split_bf16<<<dim3(3 * D_ / 32, D_ / 32), dim3(32, 8)>>>(
        Wqkv, bthi, btlo, D_, 3 * D_);

    // 2) QKV projection -> bf16 hi/lo directly
    gemm_bf16x3<true><<<dim3(3 * D_ / 128, MTOT / 128), 256, GEMM_SMEM>>>(
        ahi, alo, bthi, btlo, bqkv, nullptr, qkvh, qkvl, MTOT, 3 * D_, D_);

    // 3) attention (split-K tensor-core, x4 frags) -> bf16 hi/lo A operand
    attention_mma<<<dim3(B_ * H_, S_ / 128), 512, ATTN_SMEM>>>(qkvh, qkvl,
                                                               ahi, alo);

    // 4) transpose+split Wproj -> [1024][1024]
    transpose_split_bf16<<<dim3(D_ / 32, D_ / 32), dim3(32, 8)>>>(
        Wproj, bthi, btlo, D_, D_);

    // 5) output projection -> fp32 out
    gemm_bf16x3<false><<<dim3(D_ / 128, MTOT / 128), 256, GEMM_SMEM>>>(
        ahi, alo, bthi, btlo, bproj, out, nullptr, nullptr, MTOT, D_, D_);
}

// round 16
// speedup vs baseline: 1.5231x; 1.5231x over previous
#include <cuda_runtime.h>
#include <cuda_bf16.h>
#include <cstdint>
#include <math.h>

#define B_   2
#define S_   2048
#define D_   1024
#define H_   16
#define HD_  64
#define MTOT (B_ * S_)        // 4096

// Scratch (__device__ globals; no cudaMalloc allowed)
__device__ __nv_bfloat16 g_qkvh[MTOT * 3 * D_];   // qkv hi  (25 MB)
__device__ __nv_bfloat16 g_qkvl[MTOT * 3 * D_];   // qkv lo  (25 MB)
__device__ __nv_bfloat16 g_ahi[MTOT * D_];        // A-split hi (x, then att out)
__device__ __nv_bfloat16 g_alo[MTOT * D_];        // A-split lo
__device__ __nv_bfloat16 g_bthi[3 * D_ * D_];     // W^T hi [N][K]
__device__ __nv_bfloat16 g_btlo[3 * D_ * D_];     // W^T lo

// ---------------------------------------------------------------------------
// helpers
// ---------------------------------------------------------------------------
__device__ __forceinline__ uint32_t smem_u32(const void* p) {
    uint32_t a;
    asm("{ .reg .u64 t; cvta.to.shared.u64 t, %1; cvt.u32.u64 %0, t; }"
        : "=r"(a) : "l"(p));
    return a;
}

#define LDSM4(r0, r1, r2, r3, addr) \
    asm volatile("ldmatrix.sync.aligned.m8n8.x4.shared.b16 {%0,%1,%2,%3}, [%4];" \
                 : "=r"(r0), "=r"(r1), "=r"(r2), "=r"(r3) : "r"(addr))
#define LDSM2(r0, r1, addr) \
    asm volatile("ldmatrix.sync.aligned.m8n8.x2.shared.b16 {%0,%1}, [%2];" \
                 : "=r"(r0), "=r"(r1) : "r"(addr))
#define LDSM2T(r0, r1, addr) \
    asm volatile("ldmatrix.sync.aligned.m8n8.x2.trans.shared.b16 {%0,%1}, [%2];" \
                 : "=r"(r0), "=r"(r1) : "r"(addr))

#define MMA_BF16(c, a, b) \
    asm volatile("mma.sync.aligned.m16n8k16.row.col.f32.bf16.bf16.f32 " \
                 "{%0,%1,%2,%3}, {%4,%5,%6,%7}, {%8,%9}, {%0,%1,%2,%3};" \
                 : "+f"((c)[0]), "+f"((c)[1]), "+f"((c)[2]), "+f"((c)[3]) \
                 : "r"((a)[0]), "r"((a)[1]), "r"((a)[2]), "r"((a)[3]), \
                   "r"((b)[0]), "r"((b)[1]))

#define CP16(dst, src) \
    asm volatile("cp.async.cg.shared.global [%0], [%1], 16;" \
                 :: "r"(dst), "l"(src))
#define CP_COMMIT() asm volatile("cp.async.commit_group;" ::: "memory")
#define CP_WAIT0()  asm volatile("cp.async.wait_group 0;" ::: "memory")

__device__ __forceinline__ uint32_t pack_bf16(float a, float b) {
    __nv_bfloat162 t = __floats2bfloat162_rn(a, b);
    return *reinterpret_cast<uint32_t*>(&t);
}

// split a pair into hi bf16x2 + lo (residual) bf16x2
__device__ __forceinline__ void pack2_split(float a, float b,
                                            uint32_t& hi, uint32_t& lo) {
    __nv_bfloat162 h = __floats2bfloat162_rn(a, b);
    hi = *reinterpret_cast<uint32_t*>(&h);
    float ha = __bfloat162float(h.x), hb = __bfloat162float(h.y);
    __nv_bfloat162 l = __floats2bfloat162_rn(a - ha, b - hb);
    lo = *reinterpret_cast<uint32_t*>(&l);
}

// ---------------------------------------------------------------------------
// Prep: split fp32 -> bf16 hi/lo  (rowwise, [M][K] layout preserved)
// ---------------------------------------------------------------------------
__global__ void split_bf16(const float* __restrict__ src,
                           __nv_bfloat16* __restrict__ hi,
                           __nv_bfloat16* __restrict__ lo, int n4) {
    int i = blockIdx.x * blockDim.x + threadIdx.x;
    if (i >= n4) return;
    float4 v = ((const float4*)src)[i];
    float h0 = __bfloat162float(__float2bfloat16_rn(v.x));
    float h1 = __bfloat162float(__float2bfloat16_rn(v.y));
    float h2 = __bfloat162float(__float2bfloat16_rn(v.z));
    float h3 = __bfloat162float(__float2bfloat16_rn(v.w));
    uint2 ho, lw;
    ho.x = pack_bf16(h0, h1);
    ho.y = pack_bf16(h2, h3);
    lw.x = pack_bf16(v.x - h0, v.y - h1);
    lw.y = pack_bf16(v.z - h2, v.w - h3);
    ((uint2*)hi)[i] = ho;
    ((uint2*)lo)[i] = lw;
}

// Prep: W[K][N] fp32 -> W^T hi/lo bf16 [N][K]
__global__ void transpose_split_bf16(const float* __restrict__ W,
                                     __nv_bfloat16* __restrict__ Thi,
                                     __nv_bfloat16* __restrict__ Tlo,
                                     int K, int N) {
    __shared__ float t[32][33];
    int n0 = blockIdx.x * 32, k0 = blockIdx.y * 32;
    int tx = threadIdx.x, ty = threadIdx.y;   // 32 x 8
#pragma unroll
    for (int i = 0; i < 4; i++)
        t[ty + 8 * i][tx] = W[(size_t)(k0 + ty + 8 * i) * N + n0 + tx];
    __syncthreads();
#pragma unroll
    for (int i = 0; i < 4; i++) {
        float v = t[tx][ty + 8 * i];
        float h = __bfloat162float(__float2bfloat16_rn(v));
        size_t o = (size_t)(n0 + ty + 8 * i) * K + k0 + tx;
        Thi[o] = __float2bfloat16_rn(h);
        Tlo[o] = __float2bfloat16_rn(v - h);
    }
}

// ---------------------------------------------------------------------------
// Tensor-core GEMM (R14 exact): C = A @ W + bias, bf16 x3 split.
// SPLIT=true: write result as bf16 hi/lo pair (Chi/Clo); else fp32 C.
// ---------------------------------------------------------------------------
#define BKP 40
#define MATB (128 * BKP * 2)
#define BUFB (4 * MATB)
#define GEMM_SMEM (2 * BUFB)

template <bool SPLIT>
__global__ __launch_bounds__(256, 1)
void gemm_bf16x3(const __nv_bfloat16* __restrict__ Ahi,
                 const __nv_bfloat16* __restrict__ Alo,
                 const __nv_bfloat16* __restrict__ Bhi,
                 const __nv_bfloat16* __restrict__ Blo,
                 const float* __restrict__ bias, float* __restrict__ C,
                 __nv_bfloat16* __restrict__ Chi,
                 __nv_bfloat16* __restrict__ Clo,
                 int M, int N, int K) {
    extern __shared__ char smraw[];
    const int tid  = threadIdx.x;
    const int lane = tid & 31;
    const int wid  = tid >> 5;
    const int m0   = blockIdx.y * 128;
    const int n0   = blockIdx.x * 128;
    const int m0w  = (wid >> 2) * 64;
    const int n0w  = (wid & 3) * 32;
    const uint32_t sb = smem_u32(smraw);

    const int lrow = tid >> 1;
    const int lk   = (tid & 1) * 16;
    const __nv_bfloat16* gAh = Ahi + (size_t)(m0 + lrow) * K + lk;
    const __nv_bfloat16* gAl = Alo + (size_t)(m0 + lrow) * K + lk;
    const __nv_bfloat16* gBh = Bhi + (size_t)(n0 + lrow) * K + lk;
    const __nv_bfloat16* gBl = Blo + (size_t)(n0 + lrow) * K + lk;
    const uint32_t sdst = (uint32_t)(lrow * (BKP * 2) + lk * 2);

    float c[4][4][4] = {};

    const int arow = lane & 15;
    const int acol = (lane >> 4) * 8;
    const int bl7  = lane & 7;
    const int bk8  = ((lane >> 3) & 1) * 8;

    {
        uint4 a0 = *(const uint4*)(gAh);     uint4 a1 = *(const uint4*)(gAh + 8);
        uint4 l0 = *(const uint4*)(gAl);     uint4 l1 = *(const uint4*)(gAl + 8);
        uint4 b0 = *(const uint4*)(gBh);     uint4 b1 = *(const uint4*)(gBh + 8);
        uint4 w0 = *(const uint4*)(gBl);     uint4 w1 = *(const uint4*)(gBl + 8);
        char* p = smraw;
        *(uint4*)(p + 0 * MATB + sdst) = a0;  *(uint4*)(p + 0 * MATB + sdst + 16) = a1;
        *(uint4*)(p + 1 * MATB + sdst) = l0;  *(uint4*)(p + 1 * MATB + sdst + 16) = l1;
        *(uint4*)(p + 2 * MATB + sdst) = b0;  *(uint4*)(p + 2 * MATB + sdst + 16) = b1;
        *(uint4*)(p + 3 * MATB + sdst) = w0;  *(uint4*)(p + 3 * MATB + sdst + 16) = w1;
    }
    __syncthreads();

    int buf = 0;
    for (int k0 = 32; k0 <= K; k0 += 32) {
        uint4 a0, a1, l0, l1, b0, b1, w0, w1;
        const bool more = (k0 < K);
        if (more) {
            a0 = *(const uint4*)(gAh + k0); a1 = *(const uint4*)(gAh + k0 + 8);
            l0 = *(const uint4*)(gAl + k0); l1 = *(const uint4*)(gAl + k0 + 8);
            b0 = *(const uint4*)(gBh + k0); b1 = *(const uint4*)(gBh + k0 + 8);
            w0 = *(const uint4*)(gBl + k0); w1 = *(const uint4*)(gBl + k0 + 8);
        }

        const uint32_t bb = sb + (uint32_t)buf * BUFB;
#pragma unroll
        for (int ks = 0; ks < 2; ks++) {
            uint32_t bh[4][2], bl[4][2];
#pragma unroll
            for (int nt = 0; nt < 4; nt++) {
                uint32_t boff = (uint32_t)((n0w + nt * 8 + bl7) * (BKP * 2)
                                           + (ks * 16 + bk8) * 2);
                LDSM2(bh[nt][0], bh[nt][1], bb + 2 * MATB + boff);
                LDSM2(bl[nt][0], bl[nt][1], bb + 3 * MATB + boff);
            }
#pragma unroll
            for (int mt = 0; mt < 4; mt++) {
                uint32_t aoff = (uint32_t)((m0w + mt * 16 + arow) * (BKP * 2)
                                           + (ks * 16 + acol) * 2);
                uint32_t ah[4], al[4];
                LDSM4(ah[0], ah[1], ah[2], ah[3], bb + 0 * MATB + aoff);
                LDSM4(al[0], al[1], al[2], al[3], bb + 1 * MATB + aoff);
#pragma unroll
                for (int nt = 0; nt < 4; nt++) {
                    MMA_BF16(c[mt][nt], ah, bh[nt]);
                    MMA_BF16(c[mt][nt], ah, bl[nt]);
                    MMA_BF16(c[mt][nt], al, bh[nt]);
                }
            }
        }

        if (more) {
            char* p = smraw + (buf ^ 1) * BUFB;
            *(uint4*)(p + 0 * MATB + sdst) = a0;  *(uint4*)(p + 0 * MATB + sdst + 16) = a1;
            *(uint4*)(p + 1 * MATB + sdst) = l0;  *(uint4*)(p + 1 * MATB + sdst + 16) = l1;
            *(uint4*)(p + 2 * MATB + sdst) = b0;  *(uint4*)(p + 2 * MATB + sdst + 16) = b1;
            *(uint4*)(p + 3 * MATB + sdst) = w0;  *(uint4*)(p + 3 * MATB + sdst + 16) = w1;
            __syncthreads();
            buf ^= 1;
        }
    }

    const int erow = lane >> 2;
    const int ecol = (lane & 3) * 2;
#pragma unroll
    for (int mt = 0; mt < 4; mt++) {
#pragma unroll
        for (int nt = 0; nt < 4; nt++) {
            const int col = n0 + n0w + nt * 8 + ecol;
            const float bi0 = bias[col], bi1 = bias[col + 1];
            const int r0 = m0 + m0w + mt * 16 + erow;
            float v00 = c[mt][nt][0] + bi0, v01 = c[mt][nt][1] + bi1;
            float v10 = c[mt][nt][2] + bi0, v11 = c[mt][nt][3] + bi1;
            if (SPLIT) {
                uint32_t h0, l0v, h1, l1v;
                pack2_split(v00, v01, h0, l0v);
                pack2_split(v10, v11, h1, l1v);
                *(uint32_t*)(Chi + (size_t)r0 * N + col) = h0;
                *(uint32_t*)(Clo + (size_t)r0 * N + col) = l0v;
                *(uint32_t*)(Chi + (size_t)(r0 + 8) * N + col) = h1;
                *(uint32_t*)(Clo + (size_t)(r0 + 8) * N + col) = l1v;
            } else {
                float2 v0, v1;
                v0.x = v00; v0.y = v01;
                v1.x = v10; v1.y = v11;
                *(float2*)(C + (size_t)r0 * N + col) = v0;
                *(float2*)(C + (size_t)(r0 + 8) * N + col) = v1;
            }
        }
    }
}

// ---------------------------------------------------------------------------
// Tensor-core flash attention v5: 2 CTAs/SM for cross-CTA phase overlap.
// 256 threads (8 warps), q-tile 64, k-tile 128, split-K warps:
// warp (qg = wid>>1 in 0..3, kh = wid&1) owns q rows qg*16..+15 and
// k cols kh*64..+63. Single-buffered KV (the co-resident CTA hides loads).
// smem: Qh,Ql [64][72] + Kh,Kl,Vh,Vl [128][72] bf16 = 92160 B -> 2 CTAs/SM.
// ---------------------------------------------------------------------------
#define QP 72
#define QMAT  (64 * QP)                   // Q matrix elems
#define KVMAT (128 * QP)                  // KV matrix elems
#define ATTN_SMEM ((2 * QMAT + 4 * KVMAT) * 2)   // 92160 bytes

__global__ __launch_bounds__(256, 2)
void attention_mma(const __nv_bfloat16* __restrict__ qg_h,
                   const __nv_bfloat16* __restrict__ qg_l,
                   __nv_bfloat16* __restrict__ ohi,
                   __nv_bfloat16* __restrict__ olo) {
    extern __shared__ __nv_bfloat16 smb[];
    __nv_bfloat16* Qh = smb;              // [64][72]
    __nv_bfloat16* Ql = Qh + QMAT;
    __nv_bfloat16* Kh = Ql + QMAT;        // [128][72]
    __nv_bfloat16* Kl = Kh + KVMAT;
    __nv_bfloat16* Vh = Kl + KVMAT;
    __nv_bfloat16* Vl = Vh + KVMAT;

    const int tid  = threadIdx.x;
    const int lane = tid & 31;
    const int wid  = tid >> 5;
    const int l16  = lane & 15;
    const int qg   = wid >> 1;            // q group 0..3
    const int kh   = wid & 1;             // k half 0..1
    const int qr0  = qg * 16;

    const int bb = blockIdx.x >> 4;       // batch
    const int h  = blockIdx.x & 15;
    const int q0 = blockIdx.y * 64;

    const int qoff = h * HD_;
    const int koff = D_ + h * HD_;
    const int voff = 2 * D_ + h * HD_;

    // KV loader: row lr = tid>>1 (0..127), chunks ch0..ch0+3 of 8 (16B each)
    const int lr  = tid >> 1;
    const int ch0 = (tid & 1) * 4;
    const uint32_t sKh = smem_u32(Kh) + (uint32_t)(lr * QP + ch0 * 8) * 2;
    const uint32_t sKl = smem_u32(Kl) + (uint32_t)(lr * QP + ch0 * 8) * 2;
    const uint32_t sVh = smem_u32(Vh) + (uint32_t)(lr * QP + ch0 * 8) * 2;
    const uint32_t sVl = smem_u32(Vl) + (uint32_t)(lr * QP + ch0 * 8) * 2;

    // ---- prologue: Q + KV tile 0 ----
    {
        const int qlr  = tid >> 2;            // 0..63
        const int qch0 = (tid & 3) * 2;       // chunks 0,2,4,6 (2 each)
        const uint32_t sQh = smem_u32(Qh) + (uint32_t)(qlr * QP + qch0 * 8) * 2;
        const uint32_t sQl = smem_u32(Ql) + (uint32_t)(qlr * QP + qch0 * 8) * 2;
        const size_t qrow = (size_t)(bb * S_ + q0 + qlr) * (3 * D_) + qoff + qch0 * 8;
#pragma unroll
        for (int i = 0; i < 2; i++) {
            CP16(sQh + i * 16, qg_h + qrow + i * 8);
            CP16(sQl + i * 16, qg_l + qrow + i * 8);
        }
        const size_t krow = (size_t)(bb * S_ + lr) * (3 * D_);
#pragma unroll
        for (int i = 0; i < 4; i++) {
            CP16(sKh + i * 16, qg_h + krow + koff + (ch0 + i) * 8);
            CP16(sKl + i * 16, qg_l + krow + koff + (ch0 + i) * 8);
            CP16(sVh + i * 16, qg_h + krow + voff + (ch0 + i) * 8);
            CP16(sVl + i * 16, qg_l + krow + voff + (ch0 + i) * 8);
        }
        CP_COMMIT();
    }
    CP_WAIT0();
    __syncthreads();

    // ---- Q fragments (persistent) ----
    uint32_t qh[4][4], ql[4][4];
#pragma unroll
    for (int ks = 0; ks < 4; ks++) {
        uint32_t ao = (uint32_t)((qr0 + l16) * QP + ks * 16 + (lane >> 4) * 8) * 2;
        LDSM4(qh[ks][0], qh[ks][1], qh[ks][2], qh[ks][3], smem_u32(Qh) + ao);
        LDSM4(ql[ks][0], ql[ks][1], ql[ks][2], ql[ks][3], smem_u32(Ql) + ao);
    }

    float O[8][4] = {};
    float m0 = -1e30f, m1 = -1e30f, l0 = 0.f, l1 = 0.f;
    const float scale = 0.125f;

    // warp's k-half fragment base addresses (fixed; single buffer)
    const uint32_t kb_h = smem_u32(Kh)
        + (uint32_t)((kh * 64 + (l16 & 7)) * QP + (l16 >> 3) * 8) * 2;
    const uint32_t kb_l = smem_u32(Kl)
        + (uint32_t)((kh * 64 + (l16 & 7)) * QP + (l16 >> 3) * 8) * 2;
    const uint32_t vb_h = smem_u32(Vh) + (uint32_t)((kh * 64 + l16) * QP) * 2;
    const uint32_t vb_l = smem_u32(Vl) + (uint32_t)((kh * 64 + l16) * QP) * 2;

    for (int kt = 0; kt < S_ / 128; kt++) {
        // ---- S = QK^T over this warp's 64 cols (3-term split) ----
        float s[8][4];
#pragma unroll
        for (int nf = 0; nf < 8; nf++) {
            s[nf][0] = s[nf][1] = s[nf][2] = s[nf][3] = 0.f;
#pragma unroll
            for (int ks = 0; ks < 4; ks++) {
                const uint32_t off = (uint32_t)(nf * 8 * QP + ks * 16) * 2;
                uint32_t bh[2], bl[2];
                LDSM2(bh[0], bh[1], kb_h + off);
                LDSM2(bl[0], bl[1], kb_l + off);
                MMA_BF16(s[nf], qh[ks], bh);
                MMA_BF16(s[nf], qh[ks], bl);
                MMA_BF16(s[nf], ql[ks], bh);
            }
        }

        // ---- online softmax on fragments ----
        float mx0 = -1e30f, mx1 = -1e30f;
#pragma unroll
        for (int nf = 0; nf < 8; nf++) {
            s[nf][0] *= scale; s[nf][1] *= scale;
            s[nf][2] *= scale; s[nf][3] *= scale;
            mx0 = fmaxf(mx0, fmaxf(s[nf][0], s[nf][1]));
            mx1 = fmaxf(mx1, fmaxf(s[nf][2], s[nf][3]));
        }
        mx0 = fmaxf(mx0, __shfl_xor_sync(0xffffffffu, mx0, 1));
        mx0 = fmaxf(mx0, __shfl_xor_sync(0xffffffffu, mx0, 2));
        mx1 = fmaxf(mx1, __shfl_xor_sync(0xffffffffu, mx1, 1));
        mx1 = fmaxf(mx1, __shfl_xor_sync(0xffffffffu, mx1, 2));

        const float mn0 = fmaxf(m0, mx0);
        const float mn1 = fmaxf(m1, mx1);
        const float al0 = __expf(m0 - mn0);
        const float al1 = __expf(m1 - mn1);
        m0 = mn0; m1 = mn1;

        float rs0 = 0.f, rs1 = 0.f;
#pragma unroll
        for (int nf = 0; nf < 8; nf++) {
            s[nf][0] = __expf(s[nf][0] - m0);
            s[nf][1] = __expf(s[nf][1] - m0);
            s[nf][2] = __expf(s[nf][2] - m1);
            s[nf][3] = __expf(s[nf][3] - m1);
            rs0 += s[nf][0] + s[nf][1];
            rs1 += s[nf][2] + s[nf][3];
        }
        rs0 += __shfl_xor_sync(0xffffffffu, rs0, 1);
        rs0 += __shfl_xor_sync(0xffffffffu, rs0, 2);
        rs1 += __shfl_xor_sync(0xffffffffu, rs1, 1);
        rs1 += __shfl_xor_sync(0xffffffffu, rs1, 2);
        l0 = l0 * al0 + rs0;
        l1 = l1 * al1 + rs1;

#pragma unroll
        for (int df = 0; df < 8; df++) {
            O[df][0] *= al0; O[df][1] *= al0;
            O[df][2] *= al1; O[df][3] *= al1;
        }

        // ---- O += P @ V over this warp's 64 k-rows ----
#pragma unroll
        for (int kk = 0; kk < 4; kk++) {
            uint32_t ah[4], alr[4];
            pack2_split(s[2 * kk][0],     s[2 * kk][1],     ah[0], alr[0]);
            pack2_split(s[2 * kk][2],     s[2 * kk][3],     ah[1], alr[1]);
            pack2_split(s[2 * kk + 1][0], s[2 * kk + 1][1], ah[2], alr[2]);
            pack2_split(s[2 * kk + 1][2], s[2 * kk + 1][3], ah[3], alr[3]);
#pragma unroll
            for (int df = 0; df < 8; df++) {
                const uint32_t off = (uint32_t)(kk * 16 * QP + df * 8) * 2;
                uint32_t vb[2], vl2[2];
                LDSM2T(vb[0],  vb[1],  vb_h + off);
                LDSM2T(vl2[0], vl2[1], vb_l + off);
                MMA_BF16(O[df], ah,  vb);
                MMA_BF16(O[df], ah,  vl2);
                MMA_BF16(O[df], alr, vb);
            }
        }

        // ---- load next KV tile (single buffer; co-resident CTA hides this) ----
        if (kt + 1 < S_ / 128) {
            __syncthreads();               // all warps done reading KV
            const size_t krow = (size_t)(bb * S_ + (kt + 1) * 128 + lr) * (3 * D_);
#pragma unroll
            for (int i = 0; i < 4; i++) {
                CP16(sKh + i * 16, qg_h + krow + koff + (ch0 + i) * 8);
                CP16(sKl + i * 16, qg_l + krow + koff + (ch0 + i) * 8);
                CP16(sVh + i * 16, qg_h + krow + voff + (ch0 + i) * 8);
                CP16(sVl + i * 16, qg_l + krow + voff + (ch0 + i) * 8);
            }
            CP_COMMIT();
            CP_WAIT0();
            __syncthreads();               // new tile visible to all
        }
    }

    // ---- combine the two k-half states per q-group (via reused smem) ----
    __syncthreads();                       // all compute done; smem reusable
    float* mlb = (float*)smb;              // [4 g][2 kh][16 row][2 (m,l)]
    float* Ost = (float*)smb + 512;        // [4 g][16 row][64 col]

    const int r = lane >> 2;
    if ((lane & 3) == 0) {
        float* p = mlb + ((qg * 2 + kh) * 16 + r) * 2;
        p[0] = m0;  p[1] = l0;
        float* p8 = mlb + ((qg * 2 + kh) * 16 + r + 8) * 2;
        p8[0] = m1; p8[1] = l1;
    }
    __syncthreads();

    const float* pa0 = mlb + ((qg * 2 + 0) * 16 + r) * 2;
    const float* pb0 = mlb + ((qg * 2 + 1) * 16 + r) * 2;
    const float* pa1 = mlb + ((qg * 2 + 0) * 16 + r + 8) * 2;
    const float* pb1 = mlb + ((qg * 2 + 1) * 16 + r + 8) * 2;
    const float ma0 = pa0[0], la0 = pa0[1], mb0 = pb0[0], lb0 = pb0[1];
    const float ma1 = pa1[0], la1 = pa1[1], mb1 = pb1[0], lb1 = pb1[1];
    const float mm0 = fmaxf(ma0, mb0), mm1 = fmaxf(ma1, mb1);
    const float fa0 = __expf(ma0 - mm0), fb0 = __expf(mb0 - mm0);
    const float fa1 = __expf(ma1 - mm1), fb1 = __expf(mb1 - mm1);
    const float lc0 = la0 * fa0 + lb0 * fb0;
    const float lc1 = la1 * fa1 + lb1 * fb1;

    const int ccol = (lane & 3) * 2;
    if (kh == 1) {                         // stage scaled O of half 1
#pragma unroll
        for (int df = 0; df < 8; df++) {
            float* p0 = Ost + (qg * 16 + r) * 64 + df * 8 + ccol;
            float* p1 = Ost + (qg * 16 + r + 8) * 64 + df * 8 + ccol;
            p0[0] = O[df][0] * fb0;  p0[1] = O[df][1] * fb0;
            p1[0] = O[df][2] * fb1;  p1[1] = O[df][3] * fb1;
        }
    }
    __syncthreads();

    if (kh == 0) {                         // merge + normalize + split-store
        const float inv0 = 1.f / lc0;
        const float inv1 = 1.f / lc1;
        const int qrow = q0 + qr0 + r;
        const int cb   = h * HD_ + ccol;
#pragma unroll
        for (int df = 0; df < 8; df++) {
            const float* p0 = Ost + (qg * 16 + r) * 64 + df * 8 + ccol;
            const float* p1 = Ost + (qg * 16 + r + 8) * 64 + df * 8 + ccol;
            float v00 = (O[df][0] * fa0 + p0[0]) * inv0;
            float v01 = (O[df][1] * fa0 + p0[1]) * inv0;
            float v10 = (O[df][2] * fa1 + p1[0]) * inv1;
            float v11 = (O[df][3] * fa1 + p1[1]) * inv1;
            uint32_t h0, lv0, h1, lv1;
            pack2_split(v00, v01, h0, lv0);
            pack2_split(v10, v11, h1, lv1);
            const size_t r0 = (size_t)(bb * S_ + qrow) * D_ + cb + df * 8;
            const size_t r1 = (size_t)(bb * S_ + qrow + 8) * D_ + cb + df * 8;
            *(uint32_t*)(ohi + r0) = h0;
            *(uint32_t*)(olo + r0) = lv0;
            *(uint32_t*)(ohi + r1) = h1;
            *(uint32_t*)(olo + r1) = lv1;
        }
    }
}

// ---------------------------------------------------------------------------
extern "C" void kernel_launch(void* const* d_in, const int* in_sizes, int n_in,
                              void* d_out, int out_size) {
    const float* x     = (const float*)d_in[0];
    const float* Wqkv  = (const float*)d_in[1];
    const float* bqkv  = (const float*)d_in[2];
    const float* Wproj = (const float*)d_in[3];
    const float* bproj = (const float*)d_in[4];
    float* out = (float*)d_out;

    __nv_bfloat16 *qkvh, *qkvl, *ahi, *alo, *bthi, *btlo;
    cudaGetSymbolAddress((void**)&qkvh, g_qkvh);
    cudaGetSymbolAddress((void**)&qkvl, g_qkvl);
    cudaGetSymbolAddress((void**)&ahi,  g_ahi);
    cudaGetSymbolAddress((void**)&alo,  g_alo);
    cudaGetSymbolAddress((void**)&bthi, g_bthi);
    cudaGetSymbolAddress((void**)&btlo, g_btlo);

    cudaFuncSetAttribute(attention_mma,
                         cudaFuncAttributeMaxDynamicSharedMemorySize, ATTN_SMEM);
    cudaFuncSetAttribute(gemm_bf16x3<true>,
                         cudaFuncAttributeMaxDynamicSharedMemorySize, GEMM_SMEM);
    cudaFuncSetAttribute(gemm_bf16x3<false>,
                         cudaFuncAttributeMaxDynamicSharedMemorySize, GEMM_SMEM);

    const int n4 = MTOT * D_ / 4;

    // 1) prep: split x; transpose+split Wqkv -> [3072][1024]
    split_bf16<<<(n4 + 255) / 256, 256>>>(x, ahi, alo, n4);
    transpose_split_bf16<<<dim3(3 * D_ / 32, D_ / 32), dim3(32, 8)>>>(
        Wqkv, bthi, btlo, D_, 3 * D_);

    // 2) QKV projection -> bf16 hi/lo directly
    gemm_bf16x3<true><<<dim3(3 * D_ / 128, MTOT / 128), 256, GEMM_SMEM>>>(
        ahi, alo, bthi, btlo, bqkv, nullptr, qkvh, qkvl, MTOT, 3 * D_, D_);

    // 3) attention (split-K tensor-core, 2 CTAs/SM) -> bf16 hi/lo A operand
    attention_mma<<<dim3(B_ * H_, S_ / 64), 256, ATTN_SMEM>>>(qkvh, qkvl,
                                                              ahi, alo);

    // 4) transpose+split Wproj -> [1024][1024]
    transpose_split_bf16<<<dim3(D_ / 32, D_ / 32), dim3(32, 8)>>>(
        Wproj, bthi, btlo, D_, D_);

    // 5) output projection -> fp32 out
    gemm_bf16x3<false><<<dim3(D_ / 128, MTOT / 128), 256, GEMM_SMEM>>>(
        ahi, alo, bthi, btlo, bproj, out, nullptr, nullptr, MTOT, D_, D_);
}